// round 13
// baseline (speedup 1.0000x reference)
#include <cuda_runtime.h>
#include <cstdint>

// ============================================================================
// GCN layer on sm_103 (mma.sync tf32 HMMA path).
//   out = (D^-1/2 (A+I) D^-1/2) X W^T + b ;  B=8, N=2048, F=128, fp32.
// R11 -> R12 (gemm0 73.8us; issue 27.8%, tensor 38.1%, DRAM 26.5%;
// smem-crossbar 768cyc + deps dominate):
//   * warp tile 64x64 (1.0 LDS/MMA, R7-verified fragment map) at 8 warps via
//     intra-CTA split-K: warps w / w+4 share a tile, take p-steps {0,1}/{2,3}
//   * smem traffic 96KB -> 64KB per k-iter; partial-C reduction through
//     reused stage smem after the mainloop (one-time)
// ============================================================================

#define DINL __device__ __forceinline__

static const int BB = 8;
static const int NN = 2048;
static const int FF = 128;

static const int NSTAGES = 3;
static const int PITCH = 36;                       // floats per smem row (144B)
static const int TILE_FLOATS = 128 * PITCH;        // one operand tile
static const int STAGE_FLOATS = 2 * TILE_FLOATS;   // A then B
static const int SMEM_TOTAL = NSTAGES * STAGE_FLOATS * 4;  // 110592 B
static const int RED_PITCH = 72;                   // reduction pitch (floats)

__device__ __align__(128) float g_d[BB * NN];
__device__ __align__(128) float g_xsT[(size_t)BB * FF * NN];   // [b][f][m], tf32-rounded
__device__ __align__(128) float g_out1[(size_t)BB * NN * FF];  // [b][n][f], tf32-rounded
__device__ __align__(128) float g_Wr[FF * FF];                 // W tf32-rounded

// ---------------------------------------------------------------------------
DINL uint32_t smem_u32(const void* p) {
    uint32_t a;
    asm("{ .reg .u64 t; cvta.to.shared.u64 t, %1; cvt.u32.u64 %0, t; }"
        : "=r"(a) : "l"(p));
    return a;
}
DINL void cpasync16(uint32_t s, const void* g) {
    asm volatile("cp.async.cg.shared.global [%0], [%1], 16;"
                 :: "r"(s), "l"(g) : "memory");
}
DINL void cp_commit() { asm volatile("cp.async.commit_group;" ::: "memory"); }
template <int n> DINL void cp_wait() {
    asm volatile("cp.async.wait_group %0;" :: "n"(n) : "memory");
}
DINL uint32_t f2tf(float f) {
    uint32_t r;
    asm("cvt.rna.tf32.f32 %0, %1;" : "=r"(r) : "f"(f));
    return r;
}
DINL float f2tf_f(float f) { return __uint_as_float(f2tf(f)); }
DINL void mma_tf32(float* c, const uint32_t* a, const uint32_t* b) {
    asm volatile(
        "mma.sync.aligned.m16n8k8.row.col.f32.tf32.tf32.f32 "
        "{%0,%1,%2,%3}, {%4,%5,%6,%7}, {%8,%9}, {%0,%1,%2,%3};"
        : "+f"(c[0]), "+f"(c[1]), "+f"(c[2]), "+f"(c[3])
        : "r"(a[0]), "r"(a[1]), "r"(a[2]), "r"(a[3]), "r"(b[0]), "r"(b[1]));
}

// ---------------------------------------------------------------------------
// K0: W pre-round (tiny)
// ---------------------------------------------------------------------------
__global__ void prep_w_kernel(const float* __restrict__ W) {
    int i = blockIdx.x * blockDim.x + threadIdx.x;
    if (i < FF * FF) g_Wr[i] = f2tf_f(W[i]);
}

// ---------------------------------------------------------------------------
// K1: d[row] = rsqrt(sum(adj_row) + 1)   — warp per row, MLP=16
// ---------------------------------------------------------------------------
__global__ void __launch_bounds__(256) deg_kernel(const float* __restrict__ adj,
                                                  float* __restrict__ dout) {
    int wid = threadIdx.x >> 5, lane = threadIdx.x & 31;
    int row = blockIdx.x * 8 + wid;
    const float4* p = (const float4*)(adj + (size_t)row * NN);
    float s = 0.f;
#pragma unroll
    for (int i = 0; i < 16; i++) {
        float4 v = p[lane + i * 32];
        s += (v.x + v.y) + (v.z + v.w);
    }
#pragma unroll
    for (int o = 16; o > 0; o >>= 1) s += __shfl_down_sync(0xffffffffu, s, o);
    if (lane == 0) dout[row] = rsqrtf(s + 1.0f);
}

// ---------------------------------------------------------------------------
// K2: xsT[b][f][m] = tf32_round(d[b][m] * x[b][m][f])
// ---------------------------------------------------------------------------
__global__ void __launch_bounds__(256) xsT_kernel(const float* __restrict__ x,
                                                  const float* __restrict__ dvec,
                                                  float* __restrict__ xsT) {
    __shared__ float t[32][33];
    int b = blockIdx.z;
    int n0 = blockIdx.x * 32;
    int f0 = blockIdx.y * 32;
    int tx = threadIdx.x, ty = threadIdx.y;
#pragma unroll
    for (int j = ty; j < 32; j += 8) {
        int n = n0 + j;
        t[j][tx] = f2tf_f(x[((size_t)b * NN + n) * FF + f0 + tx] * dvec[b * NN + n]);
    }
    __syncthreads();
#pragma unroll
    for (int j = ty; j < 32; j += 8) {
        xsT[(size_t)b * FF * NN + (size_t)(f0 + j) * NN + n0 + tx] = t[tx][j];
    }
}

// ---------------------------------------------------------------------------
// K3/K4: tf32 GEMM, C[128x128] per CTA, 256 threads, 8 warps.
// Warp pairs (w, w+4) share a 64x64 tile (2x2 tile grid); w handles
// p-steps {0,1}, w+4 handles {2,3} of each 32-k chunk (intra-CTA split-K).
// After the mainloop, kg=1 partial C is reduced into kg=0 via reused smem.
//   C[r][c] = sum_k A[r][k] * Bt[c][k]
// MODE 0: A=adj (cvt.rna in-loop), Bt=xsT (pre-rounded);
//         epi: out1 = tf32_round(d_r*acc + d_r^2*x[r][c])
// MODE 1: A=out1 (pre-rounded), Bt=Wr (pre-rounded); epi: acc + bias[c]
// ---------------------------------------------------------------------------
DINL void load_stage(float* smem, int s, int k, const float* Ab, int lda,
                     const float* Bb, int ldb, int tid) {
    uint32_t base = smem_u32(smem) + (uint32_t)s * STAGE_FLOATS * 4;
#pragma unroll
    for (int i = 0; i < 4; i++) {
        int idx = tid + i * 256;             // 0..1023
        int row = idx >> 3, ch = idx & 7;
        const char* g = (const char*)Ab + (size_t)row * lda * 4 + (size_t)k * 128 + ch * 16;
        cpasync16(base + (uint32_t)row * 144 + ch * 16, g);
    }
    base += TILE_FLOATS * 4;
#pragma unroll
    for (int i = 0; i < 4; i++) {
        int idx = tid + i * 256;
        int row = idx >> 3, ch = idx & 7;
        const char* g = (const char*)Bb + (size_t)row * ldb * 4 + (size_t)k * 128 + ch * 16;
        cpasync16(base + (uint32_t)row * 144 + ch * 16, g);
    }
}

template <int MODE>
DINL void load_frag(const float* As, const float* Bs, int p, int wm, int wn,
                    int gid, int tg, uint32_t a[4][4], uint32_t bq[8][2]) {
    int kc = 8 * p + tg;
#pragma unroll
    for (int i = 0; i < 4; i++) {
        int r = wm * 64 + 16 * i + gid;
        if (MODE == 0) {
            a[i][0] = f2tf(As[r * PITCH + kc]);
            a[i][1] = f2tf(As[(r + 8) * PITCH + kc]);
            a[i][2] = f2tf(As[r * PITCH + kc + 4]);
            a[i][3] = f2tf(As[(r + 8) * PITCH + kc + 4]);
        } else {
            a[i][0] = __float_as_uint(As[r * PITCH + kc]);
            a[i][1] = __float_as_uint(As[(r + 8) * PITCH + kc]);
            a[i][2] = __float_as_uint(As[r * PITCH + kc + 4]);
            a[i][3] = __float_as_uint(As[(r + 8) * PITCH + kc + 4]);
        }
    }
#pragma unroll
    for (int j = 0; j < 8; j++) {
        int n = wn * 64 + 8 * j + gid;
        bq[j][0] = __float_as_uint(Bs[n * PITCH + kc]);
        bq[j][1] = __float_as_uint(Bs[n * PITCH + kc + 4]);
    }
}

template <int MODE>
__global__ void __launch_bounds__(256, 1) gemm_tf32(
    const float* __restrict__ Ag, int lda,
    const float* __restrict__ Bg, int ldb,
    float* __restrict__ Og,
    int num_k,
    const float* __restrict__ dvec,
    const float* __restrict__ xg,
    const float* __restrict__ bias) {
    extern __shared__ float smem[];
    int tid = threadIdx.x;
    int wid = tid >> 5;
    int lane = tid & 31;
    int gid = lane >> 2, tg = lane & 3;
    int kg = wid >> 2;                 // k-group: 0 -> p{0,1}, 1 -> p{2,3}
    int wsub = wid & 3;
    int wm = wsub >> 1, wn = wsub & 1; // 2x2 tile grid, 64x64 per tile

    const float* Abase;
    const float* Bbase;
    float* Obase;
    const float* dvb = nullptr;
    const float* xb = nullptr;
    if (MODE == 0) {
        int b = blockIdx.y;
        size_t row0 = (size_t)b * NN + blockIdx.x * 128;
        Abase = Ag + row0 * lda;
        Bbase = Bg + (size_t)b * FF * NN;
        Obase = Og + row0 * FF;
        dvb = dvec + row0;
        xb = xg + row0 * FF;
    } else {
        size_t row0 = (size_t)blockIdx.x * 128;
        Abase = Ag + row0 * lda;
        Bbase = Bg;
        Obase = Og + row0 * FF;
    }

    float C[4][8][4];
#pragma unroll
    for (int i = 0; i < 4; i++)
#pragma unroll
        for (int j = 0; j < 8; j++)
#pragma unroll
            for (int q = 0; q < 4; q++) C[i][j][q] = 0.f;

    // prologue: fill 2 stages
    load_stage(smem, 0, 0, Abase, lda, Bbase, ldb, tid);
    cp_commit();
    if (num_k > 1) load_stage(smem, 1, 1, Abase, lda, Bbase, ldb, tid);
    cp_commit();

    for (int k = 0; k < num_k; k++) {
        cp_wait<1>();
        __syncthreads();

        int nk = k + 2;
        if (nk < num_k)
            load_stage(smem, nk % NSTAGES, nk, Abase, lda, Bbase, ldb, tid);
        cp_commit();

        const float* As = smem + (k % NSTAGES) * STAGE_FLOATS;
        const float* Bs = As + TILE_FLOATS;

        // this warp's two p-steps, register double-buffered
        uint32_t a[2][4][4];
        uint32_t bq[2][8][2];
        load_frag<MODE>(As, Bs, 2 * kg, wm, wn, gid, tg, a[0], bq[0]);
#pragma unroll
        for (int pp = 0; pp < 2; pp++) {
            if (pp == 0)
                load_frag<MODE>(As, Bs, 2 * kg + 1, wm, wn, gid, tg, a[1], bq[1]);
#pragma unroll
            for (int i = 0; i < 4; i++)
#pragma unroll
                for (int j = 0; j < 8; j++) mma_tf32(C[i][j], a[pp][i], bq[pp][j]);
        }
        // no trailing __syncthreads: next iteration's top barrier (after
        // cp_wait) already orders all reads of a stage before its refill.
    }

    // ---- intra-CTA split-K reduction through reused stage smem ----
    // All data-carrying cp.async groups retired (last real group waited at
    // iter num_k-1); barrier orders final MMA smem reads before overwrite.
    __syncthreads();
    float* red = smem + (size_t)wsub * (64 * RED_PITCH);
    if (kg == 1) {
#pragma unroll
        for (int i = 0; i < 4; i++)
#pragma unroll
            for (int h = 0; h < 2; h++) {
                int r = 16 * i + 8 * h + gid;
#pragma unroll
                for (int j = 0; j < 8; j++) {
                    int c = 8 * j + 2 * tg;
                    *(float2*)&red[r * RED_PITCH + c] =
                        make_float2(C[i][j][2 * h], C[i][j][2 * h + 1]);
                }
            }
    }
    __syncthreads();
    if (kg == 1) return;

#pragma unroll
    for (int i = 0; i < 4; i++)
#pragma unroll
        for (int h = 0; h < 2; h++) {
            int r = 16 * i + 8 * h + gid;
#pragma unroll
            for (int j = 0; j < 8; j++) {
                int c = 8 * j + 2 * tg;
                float2 v = *(const float2*)&red[r * RED_PITCH + c];
                C[i][j][2 * h] += v.x;
                C[i][j][2 * h + 1] += v.y;
            }
        }

    // epilogue (kg==0 warps: 2x2 grid of 64x64 tiles)
#pragma unroll
    for (int i = 0; i < 4; i++) {
        int r = wm * 64 + 16 * i + gid;
        float d0 = 0.f, d1 = 0.f;
        if (MODE == 0) { d0 = dvb[r]; d1 = dvb[r + 8]; }
#pragma unroll
        for (int j = 0; j < 8; j++) {
            int c = wn * 64 + 8 * j + 2 * tg;
            float v0 = C[i][j][0], v1 = C[i][j][1];
            float v2 = C[i][j][2], v3 = C[i][j][3];
            if (MODE == 0) {
                v0 = f2tf_f(d0 * v0 + d0 * d0 * xb[(size_t)r * FF + c]);
                v1 = f2tf_f(d0 * v1 + d0 * d0 * xb[(size_t)r * FF + c + 1]);
                v2 = f2tf_f(d1 * v2 + d1 * d1 * xb[(size_t)(r + 8) * FF + c]);
                v3 = f2tf_f(d1 * v3 + d1 * d1 * xb[(size_t)(r + 8) * FF + c + 1]);
            } else {
                float b0 = bias[c], b1 = bias[c + 1];
                v0 += b0; v1 += b1; v2 += b0; v3 += b1;
            }
            *(float2*)(Obase + (size_t)r * FF + c) = make_float2(v0, v1);
            *(float2*)(Obase + (size_t)(r + 8) * FF + c) = make_float2(v2, v3);
        }
    }
}

// ---------------------------------------------------------------------------
extern "C" void kernel_launch(void* const* d_in, const int* in_sizes, int n_in,
                              void* d_out, int out_size) {
    (void)in_sizes; (void)n_in; (void)out_size;
    const float* x    = (const float*)d_in[0];  // [8,2048,128]
    const float* adj  = (const float*)d_in[1];  // [8,2048,2048]
    const float* W    = (const float*)d_in[2];  // [128,128]
    const float* bias = (const float*)d_in[3];  // [128]
    float* out = (float*)d_out;                 // [8,2048,128]

    float *dv, *xsT, *out1, *wr;
    cudaGetSymbolAddress((void**)&dv, g_d);
    cudaGetSymbolAddress((void**)&xsT, g_xsT);
    cudaGetSymbolAddress((void**)&out1, g_out1);
    cudaGetSymbolAddress((void**)&wr, g_Wr);

    cudaFuncSetAttribute(gemm_tf32<0>, cudaFuncAttributeMaxDynamicSharedMemorySize,
                         SMEM_TOTAL);
    cudaFuncSetAttribute(gemm_tf32<1>, cudaFuncAttributeMaxDynamicSharedMemorySize,
                         SMEM_TOTAL);

    prep_w_kernel<<<16, 1024>>>(W);
    deg_kernel<<<BB * NN / 8, 256>>>(adj, dv);
    xsT_kernel<<<dim3(NN / 32, FF / 32, BB), dim3(32, 8)>>>(x, dv, xsT);
    // aggregate GEMM: 16 M-tiles x 8 batches = 128 CTAs, K = 2048
    gemm_tf32<0><<<dim3(NN / 128, BB), 256, SMEM_TOTAL>>>(
        adj, NN, xsT, NN, out1, NN / 32, dv, x, nullptr);
    // linear: [16384,128] @ Wr^T + bias = 128 CTAs, K = 128
    gemm_tf32<1><<<dim3(BB * NN / 128, 1), 256, SMEM_TOTAL>>>(
        out1, FF, wr, FF, out, FF / 32, nullptr, nullptr, bias);
}

// round 15
// speedup vs baseline: 1.0799x; 1.0799x over previous
#include <cuda_runtime.h>
#include <cstdint>

// ============================================================================
// GCN layer on sm_103 (mma.sync tf32 HMMA path).
//   out = (D^-1/2 (A+I) D^-1/2) X W^T + b ;  B=8, N=2048, F=128, fp32.
// R14 -> R15: fix the fused-epilogue Wr smem load (was covering only 32 of
// 128 floats per W row -> rel_err 4.5). Now 128 rows x 32 x 16B chunks.
// Mainloop remains EXACTLY R11's 73.8us loop; 4-stage cp.async pipeline.
// ============================================================================

#define DINL __device__ __forceinline__

static const int BB = 8;
static const int NN = 2048;
static const int FF = 128;

static const int NSTAGES = 4;
static const int PITCH = 36;                       // floats per smem row (144B)
static const int TILE_FLOATS = 128 * PITCH;        // one operand tile
static const int STAGE_FLOATS = 2 * TILE_FLOATS;   // A then B
static const int SMEM_TOTAL = NSTAGES * STAGE_FLOATS * 4;  // 147456 B
static const int EPI_PITCH = 132;                  // epilogue pitch (floats)
// epilogue needs 2 * 128 * 132 * 4 = 135168 B <= SMEM_TOTAL  (reuses stages)

__device__ __align__(128) float g_d[BB * NN];
__device__ __align__(128) float g_xsT[(size_t)BB * FF * NN];   // [b][f][m], tf32-rounded
__device__ __align__(128) float g_Wr[FF * FF];                 // W tf32-rounded

// ---------------------------------------------------------------------------
DINL uint32_t smem_u32(const void* p) {
    uint32_t a;
    asm("{ .reg .u64 t; cvta.to.shared.u64 t, %1; cvt.u32.u64 %0, t; }"
        : "=r"(a) : "l"(p));
    return a;
}
DINL void cpasync16(uint32_t s, const void* g) {
    asm volatile("cp.async.cg.shared.global [%0], [%1], 16;"
                 :: "r"(s), "l"(g) : "memory");
}
DINL void cp_commit() { asm volatile("cp.async.commit_group;" ::: "memory"); }
template <int n> DINL void cp_wait() {
    asm volatile("cp.async.wait_group %0;" :: "n"(n) : "memory");
}
DINL uint32_t f2tf(float f) {
    uint32_t r;
    asm("cvt.rna.tf32.f32 %0, %1;" : "=r"(r) : "f"(f));
    return r;
}
DINL float f2tf_f(float f) { return __uint_as_float(f2tf(f)); }
DINL void mma_tf32(float* c, const uint32_t* a, const uint32_t* b) {
    asm volatile(
        "mma.sync.aligned.m16n8k8.row.col.f32.tf32.tf32.f32 "
        "{%0,%1,%2,%3}, {%4,%5,%6,%7}, {%8,%9}, {%0,%1,%2,%3};"
        : "+f"(c[0]), "+f"(c[1]), "+f"(c[2]), "+f"(c[3])
        : "r"(a[0]), "r"(a[1]), "r"(a[2]), "r"(a[3]), "r"(b[0]), "r"(b[1]));
}

// ---------------------------------------------------------------------------
// K0: W pre-round (tiny)
// ---------------------------------------------------------------------------
__global__ void prep_w_kernel(const float* __restrict__ W) {
    int i = blockIdx.x * blockDim.x + threadIdx.x;
    if (i < FF * FF) g_Wr[i] = f2tf_f(W[i]);
}

// ---------------------------------------------------------------------------
// K1: d[row] = rsqrt(sum(adj_row) + 1)   — warp per row, MLP=16
// ---------------------------------------------------------------------------
__global__ void __launch_bounds__(256) deg_kernel(const float* __restrict__ adj,
                                                  float* __restrict__ dout) {
    int wid = threadIdx.x >> 5, lane = threadIdx.x & 31;
    int row = blockIdx.x * 8 + wid;
    const float4* p = (const float4*)(adj + (size_t)row * NN);
    float s = 0.f;
#pragma unroll
    for (int i = 0; i < 16; i++) {
        float4 v = p[lane + i * 32];
        s += (v.x + v.y) + (v.z + v.w);
    }
#pragma unroll
    for (int o = 16; o > 0; o >>= 1) s += __shfl_down_sync(0xffffffffu, s, o);
    if (lane == 0) dout[row] = rsqrtf(s + 1.0f);
}

// ---------------------------------------------------------------------------
// K2: xsT[b][f][m] = tf32_round(d[b][m] * x[b][m][f])
// ---------------------------------------------------------------------------
__global__ void __launch_bounds__(256) xsT_kernel(const float* __restrict__ x,
                                                  const float* __restrict__ dvec,
                                                  float* __restrict__ xsT) {
    __shared__ float t[32][33];
    int b = blockIdx.z;
    int n0 = blockIdx.x * 32;
    int f0 = blockIdx.y * 32;
    int tx = threadIdx.x, ty = threadIdx.y;
#pragma unroll
    for (int j = ty; j < 32; j += 8) {
        int n = n0 + j;
        t[j][tx] = f2tf_f(x[((size_t)b * NN + n) * FF + f0 + tx] * dvec[b * NN + n]);
    }
    __syncthreads();
#pragma unroll
    for (int j = ty; j < 32; j += 8) {
        xsT[(size_t)b * FF * NN + (size_t)(f0 + j) * NN + n0 + tx] = t[tx][j];
    }
}

// ---------------------------------------------------------------------------
// K3: fused GEMM. Mainloop = R11 exactly (C[128x128]/CTA, 256 thr, 8 warps
// 4x2, warp tile 32x64, reg-double-buffered p-loop). Epilogue: out1 tile ->
// smem (scaled+rounded), Wr -> smem (FULL 512B rows), K=128 fragment GEMM,
// out += bias.
// ---------------------------------------------------------------------------
DINL void load_stage(float* smem, int s, int k, const float* Ab, int lda,
                     const float* Bb, int ldb, int tid) {
    uint32_t base = smem_u32(smem) + (uint32_t)s * STAGE_FLOATS * 4;
#pragma unroll
    for (int i = 0; i < 4; i++) {
        int idx = tid + i * 256;             // 0..1023
        int row = idx >> 3, ch = idx & 7;
        const char* g = (const char*)Ab + (size_t)row * lda * 4 + (size_t)k * 128 + ch * 16;
        cpasync16(base + (uint32_t)row * 144 + ch * 16, g);
    }
    base += TILE_FLOATS * 4;
#pragma unroll
    for (int i = 0; i < 4; i++) {
        int idx = tid + i * 256;
        int row = idx >> 3, ch = idx & 7;
        const char* g = (const char*)Bb + (size_t)row * ldb * 4 + (size_t)k * 128 + ch * 16;
        cpasync16(base + (uint32_t)row * 144 + ch * 16, g);
    }
}

DINL void load_frag(const float* As, const float* Bs, int p, int wm, int wn,
                    int gid, int tg, uint32_t a[2][4], uint32_t bq[8][2]) {
    int kc = 8 * p + tg;
#pragma unroll
    for (int i = 0; i < 2; i++) {
        int r = wm * 32 + 16 * i + gid;
        a[i][0] = f2tf(As[r * PITCH + kc]);
        a[i][1] = f2tf(As[(r + 8) * PITCH + kc]);
        a[i][2] = f2tf(As[r * PITCH + kc + 4]);
        a[i][3] = f2tf(As[(r + 8) * PITCH + kc + 4]);
    }
#pragma unroll
    for (int j = 0; j < 8; j++) {
        int n = wn * 64 + 8 * j + gid;
        bq[j][0] = __float_as_uint(Bs[n * PITCH + kc]);
        bq[j][1] = __float_as_uint(Bs[n * PITCH + kc + 4]);
    }
}

__global__ void __launch_bounds__(256, 1) gemm_fused(
    const float* __restrict__ Ag, int lda,
    const float* __restrict__ Bg, int ldb,
    float* __restrict__ Og,
    int num_k,
    const float* __restrict__ dvec,
    const float* __restrict__ xg,
    const float* __restrict__ bias) {
    extern __shared__ float smem[];
    int tid = threadIdx.x;
    int wid = tid >> 5;
    int lane = tid & 31;
    int gid = lane >> 2, tg = lane & 3;
    int wm = wid >> 1, wn = wid & 1;  // warp grid 4x2, warp tile 32x64

    int b = blockIdx.y;
    size_t row0 = (size_t)b * NN + blockIdx.x * 128;
    const float* Abase = Ag + row0 * lda;
    const float* Bbase = Bg + (size_t)b * FF * NN;
    float* Obase = Og + row0 * FF;
    const float* dvb = dvec + row0;
    const float* xb = xg + row0 * FF;

    float C[2][8][4];
#pragma unroll
    for (int i = 0; i < 2; i++)
#pragma unroll
        for (int j = 0; j < 8; j++)
#pragma unroll
            for (int q = 0; q < 4; q++) C[i][j][q] = 0.f;

    // prologue: fill 3 stages
    load_stage(smem, 0, 0, Abase, lda, Bbase, ldb, tid);
    cp_commit();
    load_stage(smem, 1, 1, Abase, lda, Bbase, ldb, tid);
    cp_commit();
    load_stage(smem, 2, 2, Abase, lda, Bbase, ldb, tid);
    cp_commit();

    for (int k = 0; k < num_k; k++) {
        cp_wait<2>();
        __syncthreads();

        int nk = k + 3;
        if (nk < num_k)
            load_stage(smem, nk % NSTAGES, nk, Abase, lda, Bbase, ldb, tid);
        cp_commit();

        const float* As = smem + (k % NSTAGES) * STAGE_FLOATS;
        const float* Bs = As + TILE_FLOATS;

        // register double-buffered p-pipeline (R11)
        uint32_t a[2][2][4];
        uint32_t bq[2][8][2];
        load_frag(As, Bs, 0, wm, wn, gid, tg, a[0], bq[0]);
#pragma unroll
        for (int p = 0; p < 4; p++) {
            int cur = p & 1, nxt = cur ^ 1;
            if (p < 3)
                load_frag(As, Bs, p + 1, wm, wn, gid, tg, a[nxt], bq[nxt]);
#pragma unroll
            for (int i = 0; i < 2; i++)
#pragma unroll
                for (int j = 0; j < 8; j++) mma_tf32(C[i][j], a[cur][i], bq[cur][j]);
        }
    }

    // ---- fused epilogue ----
    // All real cp.async groups retired (group k waited at iter k); barrier
    // orders last MMA smem reads before the stage area is overwritten.
    __syncthreads();
    float* o1s = smem;                       // 128 x EPI_PITCH (out1 tile)
    float* wrs = smem + 128 * EPI_PITCH;     // 128 x EPI_PITCH (Wr, k-major)

    // out1 tile: scale + self-loop + tf32 round -> smem
#pragma unroll
    for (int i = 0; i < 2; i++) {
        int r = wm * 32 + 16 * i + gid;
        float d0 = dvb[r], d1 = dvb[r + 8];
#pragma unroll
        for (int j = 0; j < 8; j++) {
            int c = wn * 64 + 8 * j + 2 * tg;
            float v0 = f2tf_f(d0 * C[i][j][0] + d0 * d0 * xb[(size_t)r * FF + c]);
            float v1 = f2tf_f(d0 * C[i][j][1] + d0 * d0 * xb[(size_t)r * FF + c + 1]);
            float v2 = f2tf_f(d1 * C[i][j][2] + d1 * d1 * xb[(size_t)(r + 8) * FF + c]);
            float v3 = f2tf_f(d1 * C[i][j][3] + d1 * d1 * xb[(size_t)(r + 8) * FF + c + 1]);
            *(float2*)&o1s[r * EPI_PITCH + c] = make_float2(v0, v1);
            *(float2*)&o1s[(r + 8) * EPI_PITCH + c] = make_float2(v2, v3);
        }
    }
    // Wr -> smem: FULL rows (128 rows x 128 floats = 32 x 16B chunks/row)
    {
        uint32_t wbase = smem_u32(wrs);
#pragma unroll
        for (int i = 0; i < 16; i++) {
            int idx = tid + i * 256;         // 0..4095
            int row = idx >> 5, ch = idx & 31;
            cpasync16(wbase + (uint32_t)row * (EPI_PITCH * 4) + ch * 16,
                      g_Wr + row * FF + ch * 4);
        }
        cp_commit();
        cp_wait<0>();
    }
    __syncthreads();

    // K=128 fragment GEMM: out[r][o] = sum_f o1s[r][f] * wrs[o][f]
#pragma unroll
    for (int i = 0; i < 2; i++)
#pragma unroll
        for (int j = 0; j < 8; j++)
#pragma unroll
            for (int q = 0; q < 4; q++) C[i][j][q] = 0.f;

#pragma unroll 4
    for (int p = 0; p < 16; p++) {
        int kc = 8 * p + tg;
        uint32_t a2[2][4];
#pragma unroll
        for (int i = 0; i < 2; i++) {
            int r = wm * 32 + 16 * i + gid;
            a2[i][0] = __float_as_uint(o1s[r * EPI_PITCH + kc]);
            a2[i][1] = __float_as_uint(o1s[(r + 8) * EPI_PITCH + kc]);
            a2[i][2] = __float_as_uint(o1s[r * EPI_PITCH + kc + 4]);
            a2[i][3] = __float_as_uint(o1s[(r + 8) * EPI_PITCH + kc + 4]);
        }
        uint32_t b2[8][2];
#pragma unroll
        for (int j = 0; j < 8; j++) {
            int n = wn * 64 + 8 * j + gid;
            b2[j][0] = __float_as_uint(wrs[n * EPI_PITCH + kc]);
            b2[j][1] = __float_as_uint(wrs[n * EPI_PITCH + kc + 4]);
        }
#pragma unroll
        for (int i = 0; i < 2; i++)
#pragma unroll
            for (int j = 0; j < 8; j++) mma_tf32(C[i][j], a2[i], b2[j]);
    }

    // final store with bias
#pragma unroll
    for (int i = 0; i < 2; i++) {
        int r = wm * 32 + 16 * i + gid;
#pragma unroll
        for (int j = 0; j < 8; j++) {
            int c = wn * 64 + 8 * j + 2 * tg;
            float b0 = bias[c], b1 = bias[c + 1];
            *(float2*)(Obase + (size_t)r * FF + c) =
                make_float2(C[i][j][0] + b0, C[i][j][1] + b1);
            *(float2*)(Obase + (size_t)(r + 8) * FF + c) =
                make_float2(C[i][j][2] + b0, C[i][j][3] + b1);
        }
    }
}

// ---------------------------------------------------------------------------
extern "C" void kernel_launch(void* const* d_in, const int* in_sizes, int n_in,
                              void* d_out, int out_size) {
    (void)in_sizes; (void)n_in; (void)out_size;
    const float* x    = (const float*)d_in[0];  // [8,2048,128]
    const float* adj  = (const float*)d_in[1];  // [8,2048,2048]
    const float* W    = (const float*)d_in[2];  // [128,128]
    const float* bias = (const float*)d_in[3];  // [128]
    float* out = (float*)d_out;                 // [8,2048,128]

    float *dv, *xsT;
    cudaGetSymbolAddress((void**)&dv, g_d);
    cudaGetSymbolAddress((void**)&xsT, g_xsT);

    cudaFuncSetAttribute(gemm_fused, cudaFuncAttributeMaxDynamicSharedMemorySize,
                         SMEM_TOTAL);

    prep_w_kernel<<<16, 1024>>>(W);
    deg_kernel<<<BB * NN / 8, 256>>>(adj, dv);
    xsT_kernel<<<dim3(NN / 32, FF / 32, BB), dim3(32, 8)>>>(x, dv, xsT);
    // fused aggregate+linear GEMM: 16 M-tiles x 8 batches = 128 CTAs, K=2048
    gemm_fused<<<dim3(NN / 128, BB), 256, SMEM_TOTAL>>>(
        adj, NN, xsT, NN, out, NN / 32, dv, x, bias);
}